// round 9
// baseline (speedup 1.0000x reference)
#include <cuda_runtime.h>
#include <cuda_bf16.h>

#define FULL_MASK 0xffffffffu
#define EPS 1e-6f

// One warp per (b,k) row of T=8000. Lane holds 4 consecutive timesteps
// (62 float4 iterations = 7936 elems) + one float2 tail iteration (64 elems).
//
// Recurrence f[t] = a*f[t-1] + s*x[t], a = 1-s, seeded with carry c = x[0]:
// f[0] = a*x0 + s*x0 = x0, matching the reference init exactly.
// Warp scan of the affine recurrence: per-lane local fold, then 5-step
// Hillis-Steele shuffle scan with constant multiplier (a^4 main, a^2 tail).
//
// Streaming cache hints: no inter-CTA reuse and working set (262 MB) > L2
// (126 MB), so bulk traffic uses ld.global.cs / st.global.cs (evict-first).
// Unroll bounded to 2: keeps body in L0 I$ and MLP_p1 low (cross-CTA
// L1tex-queue spread model), row-parallelism supplies the memory MLP.

// Fast base-2 exp via MUFU EX2 (there is no __exp2f intrinsic; this
// guarantees a single ex2.approx regardless of harness fast-math flags).
__device__ __forceinline__ float fast_exp2(float v) {
    float r;
    asm("ex2.approx.ftz.f32 %0, %1;" : "=f"(r) : "f"(v));
    return r;
}

__device__ __forceinline__ float pcen_elem(float xv, float fv,
                                           float nalpha, float delta,
                                           float r, float deltar) {
    float d = fv + EPS;
    float p = fast_exp2(nalpha * __log2f(d));   // d^-alpha
    float u = fmaf(xv, p, delta);
    return fast_exp2(r * __log2f(u)) - deltar;  // u^r - delta^r
}

__global__ __launch_bounds__(256) void pcen_kernel(
    const float* __restrict__ x,
    const float* __restrict__ log_s,
    const float* __restrict__ log_alpha,
    const float* __restrict__ log_delta,
    const float* __restrict__ log_r,
    float* __restrict__ out,
    int n_rows, int K)
{
    const int warp = (int)((blockIdx.x * blockDim.x + threadIdx.x) >> 5);
    if (warp >= n_rows) return;
    const int lane = threadIdx.x & 31;
    const int k = warp % K;

    // Per-channel parameters (one-time cost; tiny, cached reads)
    const float s     = 1.0f / (1.0f + __expf(-__ldg(&log_s[k])));
    const float a     = 1.0f - s;
    const float alpha = __expf(__ldg(&log_alpha[k]));
    const float delta = __expf(__ldg(&log_delta[k]));
    const float r     = __expf(__ldg(&log_r[k]));
    const float deltar = powf(delta, r);
    const float nalpha = -alpha;

    // Power table: shared by main (B-chain) and tail (A-chain) scans
    const float A   = a * a;       // a^2
    const float a3  = a * A;       // a^3
    const float B   = A * A;       // a^4   main scan step / tail step^2
    const float B2  = B * B;       // a^8
    const float B4  = B2 * B2;     // a^16
    const float B8  = B4 * B4;     // a^32
    const float B16 = B8 * B8;     // a^64  tail carry decay
    const float B32 = B16 * B16;   // a^128 main carry decay
    const float a2l = powf(a, (float)(2 * lane));  // a^(2*lane), tail
    const float a4l = a2l * a2l;                   // a^(4*lane), main

    const size_t base = (size_t)warp * 8000u;
    const float4* __restrict__ xin4 = (const float4*)(x + base);
    float4* __restrict__ out4       = (float4*)(out + base);

    // carry = f just before the first element of the next chunk; seed x[0]
    float c = __ldg(x + base);

    #pragma unroll 2
    for (int i = 0; i < 62; ++i) {
        float4 v = __ldcs(xin4 + i * 32 + lane);

        // Local fold of 4 elements (zero-carry partials)
        float l0 = s * v.x;
        float l1 = fmaf(a, l0, s * v.y);
        float l2 = fmaf(a, l1, s * v.z);
        float l3 = fmaf(a, l2, s * v.w);

        // Inclusive warp scan of l3, step multiplier B = a^4
        float z = l3, t;
        t = __shfl_up_sync(FULL_MASK, z, 1);  if (lane >= 1)  z = fmaf(B,   t, z);
        t = __shfl_up_sync(FULL_MASK, z, 2);  if (lane >= 2)  z = fmaf(B2,  t, z);
        t = __shfl_up_sync(FULL_MASK, z, 4);  if (lane >= 4)  z = fmaf(B4,  t, z);
        t = __shfl_up_sync(FULL_MASK, z, 8);  if (lane >= 8)  z = fmaf(B8,  t, z);
        t = __shfl_up_sync(FULL_MASK, z, 16); if (lane >= 16) z = fmaf(B16, t, z);

        float zex = __shfl_up_sync(FULL_MASK, z, 1);
        if (lane == 0) zex = 0.0f;
        float z31 = __shfl_sync(FULL_MASK, z, 31);

        // Carry entering this lane = a^(4*lane) * c + exclusive scan
        float carry = fmaf(a4l, c, zex);
        float f0 = fmaf(a,  carry, l0);
        float f1 = fmaf(A,  carry, l1);
        float f2 = fmaf(a3, carry, l2);
        float f3 = fmaf(B,  carry, l3);

        // Cross-iteration carry: single FMA on the dependence chain
        c = fmaf(B32, c, z31);

        float o0 = pcen_elem(v.x, f0, nalpha, delta, r, deltar);
        float o1 = pcen_elem(v.y, f1, nalpha, delta, r, deltar);
        float o2 = pcen_elem(v.z, f2, nalpha, delta, r, deltar);
        float o3 = pcen_elem(v.w, f3, nalpha, delta, r, deltar);

        __stcs(out4 + i * 32 + lane, make_float4(o0, o1, o2, o3));
    }

    // Tail: 64 elements at float offset 7936, 2 per lane, step multiplier a^2
    {
        const float2* __restrict__ xin2 = (const float2*)(x + base + 7936);
        float2* __restrict__ out2       = (float2*)(out + base + 7936);
        float2 v = __ldcs(xin2 + lane);

        float l0 = s * v.x;
        float l1 = fmaf(a, l0, s * v.y);

        float z = l1, t;
        t = __shfl_up_sync(FULL_MASK, z, 1);  if (lane >= 1)  z = fmaf(A,  t, z);
        t = __shfl_up_sync(FULL_MASK, z, 2);  if (lane >= 2)  z = fmaf(B,  t, z);
        t = __shfl_up_sync(FULL_MASK, z, 4);  if (lane >= 4)  z = fmaf(B2, t, z);
        t = __shfl_up_sync(FULL_MASK, z, 8);  if (lane >= 8)  z = fmaf(B4, t, z);
        t = __shfl_up_sync(FULL_MASK, z, 16); if (lane >= 16) z = fmaf(B8, t, z);

        float zex = __shfl_up_sync(FULL_MASK, z, 1);
        if (lane == 0) zex = 0.0f;

        float carry = fmaf(a2l, c, zex);
        float f0 = fmaf(a, carry, l0);
        float f1 = fmaf(A, carry, l1);

        float o0 = pcen_elem(v.x, f0, nalpha, delta, r, deltar);
        float o1 = pcen_elem(v.y, f1, nalpha, delta, r, deltar);

        __stcs(out2 + lane, make_float2(o0, o1));
    }
}

extern "C" void kernel_launch(void* const* d_in, const int* in_sizes, int n_in,
                              void* d_out, int out_size) {
    const float* x  = (const float*)d_in[0];
    const float* ls = (const float*)d_in[1];
    const float* la = (const float*)d_in[2];
    const float* ld = (const float*)d_in[3];
    const float* lr = (const float*)d_in[4];
    float* out = (float*)d_out;

    const int T = 8000;
    const int K = in_sizes[1];                 // 128
    const int n_rows = in_sizes[0] / T;        // 4096

    const int threads = 256;                   // 8 warps/block
    const int warps_per_block = threads / 32;
    const int blocks = (n_rows + warps_per_block - 1) / warps_per_block;

    pcen_kernel<<<blocks, threads>>>(x, ls, la, ld, lr, out, n_rows, K);
}